// round 1
// baseline (speedup 1.0000x reference)
#include <cuda_runtime.h>
#include <math.h>

// Problem constants
#define BATCH 16
#define SEQ   1024
#define DMODEL 512
#define NHEAD 4
#define HDIM  128
#define MROWS (BATCH * SEQ)   // 16384
#define DMLP  1024

// ---------------- scratch (device globals; no allocation allowed) ----------
__device__ float g_x1n [MROWS * DMODEL];
__device__ float g_x2n [MROWS * DMODEL];
__device__ float g_q   [MROWS * DMODEL];
__device__ float g_k   [MROWS * DMODEL];
__device__ float g_v   [MROWS * DMODEL];
__device__ float g_ctx [MROWS * DMODEL];
__device__ float g_src1[MROWS * DMODEL];
__device__ float g_src2[MROWS * DMODEL];
__device__ float g_xres[MROWS * DMODEL];
__device__ float g_h   [MROWS * DMLP];

// ---------------- LayerNorm: one block (128 thr) per row of 512 ------------
__global__ void ln_kernel(const float* __restrict__ x,
                          const float* __restrict__ g,
                          const float* __restrict__ b,
                          float* __restrict__ y) {
    int row = blockIdx.x;
    const float* xr = x + (size_t)row * DMODEL;
    float*       yr = y + (size_t)row * DMODEL;
    int t = threadIdx.x;               // 0..127, each owns one float4
    float4 v4 = ((const float4*)xr)[t];

    __shared__ float red[4];
    float s = v4.x + v4.y + v4.z + v4.w;
    #pragma unroll
    for (int o = 16; o; o >>= 1) s += __shfl_xor_sync(0xffffffffu, s, o);
    if ((t & 31) == 0) red[t >> 5] = s;
    __syncthreads();
    float mean = (red[0] + red[1] + red[2] + red[3]) * (1.0f / DMODEL);
    __syncthreads();

    float dx = v4.x - mean, dy = v4.y - mean, dz = v4.z - mean, dw = v4.w - mean;
    float vs = dx*dx + dy*dy + dz*dz + dw*dw;
    #pragma unroll
    for (int o = 16; o; o >>= 1) vs += __shfl_xor_sync(0xffffffffu, vs, o);
    if ((t & 31) == 0) red[t >> 5] = vs;
    __syncthreads();
    float var = (red[0] + red[1] + red[2] + red[3]) * (1.0f / DMODEL);
    float inv = rsqrtf(var + 1e-6f);

    float4 g4 = ((const float4*)g)[t];
    float4 b4 = ((const float4*)b)[t];
    float4 o4;
    o4.x = dx * inv * g4.x + b4.x;
    o4.y = dy * inv * g4.y + b4.y;
    o4.z = dz * inv * g4.z + b4.z;
    o4.w = dw * inv * g4.w + b4.w;
    ((float4*)yr)[t] = o4;
}

// ---------------- Tiled SGEMM: C = A[M,K] @ W[K,N] + bias (+resid)(+gelu) --
// 64x64 tile, BK=16, 256 threads, 4x4 per thread.
#define ACT_NONE 0
#define ACT_GELU 1
__global__ void sgemm_kernel(const float* __restrict__ A,
                             const float* __restrict__ W,
                             const float* __restrict__ bias,
                             const float* __restrict__ resid,
                             float* __restrict__ C,
                             int M, int N, int K, int act) {
    __shared__ float As[16][68];   // transposed A tile, padded
    __shared__ float Bs[16][64];
    int tid = threadIdx.x;
    int tx = tid & 15, ty = tid >> 4;
    int m0 = blockIdx.y * 64, n0 = blockIdx.x * 64;

    float c[4][4] = {};
    int ac = tid & 15;     // k within tile
    int ar = tid >> 4;     // row base

    for (int k0 = 0; k0 < K; k0 += 16) {
        #pragma unroll
        for (int i = 0; i < 4; i++)
            As[ac][ar + 16 * i] = A[(size_t)(m0 + ar + 16 * i) * K + k0 + ac];
        {
            int li = tid * 4;
            int bk = li >> 6, bn = li & 63;
            *(float4*)&Bs[bk][bn] =
                *(const float4*)&W[(size_t)(k0 + bk) * N + n0 + bn];
        }
        __syncthreads();
        #pragma unroll
        for (int kk = 0; kk < 16; kk++) {
            float4 a4 = *(const float4*)&As[kk][ty * 4];
            float4 b4 = *(const float4*)&Bs[kk][tx * 4];
            float a[4] = {a4.x, a4.y, a4.z, a4.w};
            float bb[4] = {b4.x, b4.y, b4.z, b4.w};
            #pragma unroll
            for (int i = 0; i < 4; i++)
                #pragma unroll
                for (int j = 0; j < 4; j++)
                    c[i][j] += a[i] * bb[j];
        }
        __syncthreads();
    }

    #pragma unroll
    for (int i = 0; i < 4; i++) {
        int m = m0 + ty * 4 + i;
        #pragma unroll
        for (int j = 0; j < 4; j++) {
            int n = n0 + tx * 4 + j;
            float val = c[i][j] + bias[n];
            if (resid) val += resid[(size_t)m * N + n];
            if (act == ACT_GELU)
                val = 0.5f * val * (1.0f + erff(val * 0.70710678118654752f));
            C[(size_t)m * N + n] = val;
        }
    }
}

// ---------------- Flash attention (fp32, online softmax) -------------------
// grid: (SEQ/64, NHEAD, BATCH), 256 threads.
// Thread t: q-row qr = t>>2 (64 rows), lane-in-row lq = t&3.
// k-cols handled per chunk: lq + 4*jj (jj=0..7). Output dims: lq*4 + 16*j.
#define BQ 64
#define BKC 32
#define QPAD 132
#define PPAD 33
__global__ void attn_kernel(const float* __restrict__ Q,
                            const float* __restrict__ K,
                            const float* __restrict__ V,
                            float* __restrict__ O) {
    extern __shared__ float sm[];
    float* Qs = sm;                      // [64][132]
    float* Ks = Qs + BQ  * QPAD;         // [32][132]
    float* Vs = Ks + BKC * QPAD;         // [32][132]
    float* Ps = Vs + BKC * QPAD;         // [64][33]

    int qt = blockIdx.x, h = blockIdx.y, b = blockIdx.z;
    int t = threadIdx.x;
    int qr = t >> 2, lq = t & 3;
    size_t base = ((size_t)b * SEQ) * DMODEL + (size_t)h * HDIM;
    int q0 = qt * BQ;

    // stage Q tile
    for (int idx = t; idx < BQ * HDIM / 4; idx += 256) {
        int r = idx >> 5, c4 = idx & 31;
        *(float4*)&Qs[r * QPAD + c4 * 4] =
            *(const float4*)&Q[base + (size_t)(q0 + r) * DMODEL + c4 * 4];
    }

    float acc[32];
    #pragma unroll
    for (int i = 0; i < 32; i++) acc[i] = 0.f;
    float mrow = -INFINITY, lrow = 0.f;
    const float scale = 0.08838834764831845f;   // 1/sqrt(128)

    for (int kc0 = 0; kc0 < SEQ; kc0 += BKC) {
        __syncthreads();
        for (int idx = t; idx < BKC * HDIM / 4; idx += 256) {
            int r = idx >> 5, c4 = idx & 31;
            *(float4*)&Ks[r * QPAD + c4 * 4] =
                *(const float4*)&K[base + (size_t)(kc0 + r) * DMODEL + c4 * 4];
            *(float4*)&Vs[r * QPAD + c4 * 4] =
                *(const float4*)&V[base + (size_t)(kc0 + r) * DMODEL + c4 * 4];
        }
        __syncthreads();

        // scores: s[jj] for k-col = lq + 4*jj
        float s[8];
        #pragma unroll
        for (int jj = 0; jj < 8; jj++) s[jj] = 0.f;
        #pragma unroll
        for (int d = 0; d < HDIM; d += 4) {
            float4 q4 = *(const float4*)&Qs[qr * QPAD + d];
            #pragma unroll
            for (int jj = 0; jj < 8; jj++) {
                float4 k4 = *(const float4*)&Ks[(lq + 4 * jj) * QPAD + d];
                s[jj] += q4.x * k4.x + q4.y * k4.y + q4.z * k4.z + q4.w * k4.w;
            }
        }

        float mc = -INFINITY;
        #pragma unroll
        for (int jj = 0; jj < 8; jj++) { s[jj] *= scale; mc = fmaxf(mc, s[jj]); }
        mc = fmaxf(mc, __shfl_xor_sync(0xffffffffu, mc, 1));
        mc = fmaxf(mc, __shfl_xor_sync(0xffffffffu, mc, 2));
        float mnew = fmaxf(mrow, mc);
        float corr = __expf(mrow - mnew);
        float psum = 0.f;
        #pragma unroll
        for (int jj = 0; jj < 8; jj++) {
            s[jj] = __expf(s[jj] - mnew);
            psum += s[jj];
            Ps[qr * PPAD + lq + 4 * jj] = s[jj];
        }
        psum += __shfl_xor_sync(0xffffffffu, psum, 1);
        psum += __shfl_xor_sync(0xffffffffu, psum, 2);
        lrow = lrow * corr + psum;
        mrow = mnew;
        #pragma unroll
        for (int i = 0; i < 32; i++) acc[i] *= corr;
        __syncwarp();

        // P @ V
        #pragma unroll
        for (int kc = 0; kc < BKC; kc++) {
            float p = Ps[qr * PPAD + kc];
            #pragma unroll
            for (int j = 0; j < 8; j++) {
                float4 v4 = *(const float4*)&Vs[kc * QPAD + lq * 4 + 16 * j];
                acc[j * 4 + 0] += p * v4.x;
                acc[j * 4 + 1] += p * v4.y;
                acc[j * 4 + 2] += p * v4.z;
                acc[j * 4 + 3] += p * v4.w;
            }
        }
    }

    float inv = 1.0f / lrow;
    #pragma unroll
    for (int j = 0; j < 8; j++) {
        float4 o4 = make_float4(acc[j * 4 + 0] * inv, acc[j * 4 + 1] * inv,
                                acc[j * 4 + 2] * inv, acc[j * 4 + 3] * inv);
        *(float4*)&O[base + (size_t)(q0 + qr) * DMODEL + lq * 4 + 16 * j] = o4;
    }
}

// ---------------- driver ----------------------------------------------------
extern "C" void kernel_launch(void* const* d_in, const int* in_sizes, int n_in,
                              void* d_out, int out_size) {
    const float* x1    = (const float*)d_in[0];
    const float* x2    = (const float*)d_in[1];
    const float* ln1_g = (const float*)d_in[2];
    const float* ln1_b = (const float*)d_in[3];
    const float* ln2_g = (const float*)d_in[4];
    const float* ln2_b = (const float*)d_in[5];
    const float* lnf_g = (const float*)d_in[6];
    const float* lnf_b = (const float*)d_in[7];
    const float* Wq1  = (const float*)d_in[8];   const float* bq1  = (const float*)d_in[9];
    const float* Wk1  = (const float*)d_in[10];  const float* bk1  = (const float*)d_in[11];
    const float* Wv1  = (const float*)d_in[12];  const float* bv1  = (const float*)d_in[13];
    const float* Wq2  = (const float*)d_in[14];  const float* bq2  = (const float*)d_in[15];
    const float* Wk2  = (const float*)d_in[16];  const float* bk2  = (const float*)d_in[17];
    const float* Wv2  = (const float*)d_in[18];  const float* bv2  = (const float*)d_in[19];
    const float* Wq12 = (const float*)d_in[20];  const float* bq12 = (const float*)d_in[21];
    const float* Wk12 = (const float*)d_in[22];  const float* bk12 = (const float*)d_in[23];
    const float* Wv12 = (const float*)d_in[24];  const float* bv12 = (const float*)d_in[25];
    const float* Wo   = (const float*)d_in[26];  const float* bo   = (const float*)d_in[27];
    const float* W1   = (const float*)d_in[28];  const float* b1   = (const float*)d_in[29];
    const float* W2   = (const float*)d_in[30];  const float* b2   = (const float*)d_in[31];
    float* out = (float*)d_out;

    float *x1n, *x2n, *q, *k, *v, *ctx, *src1, *src2, *xres, *hbuf;
    cudaGetSymbolAddress((void**)&x1n,  g_x1n);
    cudaGetSymbolAddress((void**)&x2n,  g_x2n);
    cudaGetSymbolAddress((void**)&q,    g_q);
    cudaGetSymbolAddress((void**)&k,    g_k);
    cudaGetSymbolAddress((void**)&v,    g_v);
    cudaGetSymbolAddress((void**)&ctx,  g_ctx);
    cudaGetSymbolAddress((void**)&src1, g_src1);
    cudaGetSymbolAddress((void**)&src2, g_src2);
    cudaGetSymbolAddress((void**)&xres, g_xres);
    cudaGetSymbolAddress((void**)&hbuf, g_h);

    const int ATTN_SMEM = (BQ * QPAD + 2 * BKC * QPAD + BQ * PPAD) * (int)sizeof(float);
    cudaFuncSetAttribute(attn_kernel, cudaFuncAttributeMaxDynamicSharedMemorySize, ATTN_SMEM);

    dim3 gAttn(SEQ / BQ, NHEAD, BATCH);
    dim3 g512 (DMODEL / 64, MROWS / 64);
    dim3 g1024(DMLP   / 64, MROWS / 64);

    // normalize both streams
    ln_kernel<<<MROWS, 128>>>(x1, ln1_g, ln1_b, x1n);
    ln_kernel<<<MROWS, 128>>>(x2, ln2_g, ln2_b, x2n);

    // stream-1 self-attention
    sgemm_kernel<<<g512, 256>>>(x1n, Wq1, bq1, nullptr, q, MROWS, DMODEL, DMODEL, ACT_NONE);
    sgemm_kernel<<<g512, 256>>>(x1n, Wk1, bk1, nullptr, k, MROWS, DMODEL, DMODEL, ACT_NONE);
    sgemm_kernel<<<g512, 256>>>(x1n, Wv1, bv1, nullptr, v, MROWS, DMODEL, DMODEL, ACT_NONE);
    attn_kernel<<<gAttn, 256, ATTN_SMEM>>>(q, k, v, ctx);
    sgemm_kernel<<<g512, 256>>>(ctx, Wo, bo, x1n, src1, MROWS, DMODEL, DMODEL, ACT_NONE);

    // stream-2 self-attention
    sgemm_kernel<<<g512, 256>>>(x2n, Wq2, bq2, nullptr, q, MROWS, DMODEL, DMODEL, ACT_NONE);
    sgemm_kernel<<<g512, 256>>>(x2n, Wk2, bk2, nullptr, k, MROWS, DMODEL, DMODEL, ACT_NONE);
    sgemm_kernel<<<g512, 256>>>(x2n, Wv2, bv2, nullptr, v, MROWS, DMODEL, DMODEL, ACT_NONE);
    attn_kernel<<<gAttn, 256, ATTN_SMEM>>>(q, k, v, ctx);
    sgemm_kernel<<<g512, 256>>>(ctx, Wo, bo, x2n, src2, MROWS, DMODEL, DMODEL, ACT_NONE);

    // cross attention: Q from src1, K/V from src2
    sgemm_kernel<<<g512, 256>>>(src1, Wq12, bq12, nullptr, q, MROWS, DMODEL, DMODEL, ACT_NONE);
    sgemm_kernel<<<g512, 256>>>(src2, Wk12, bk12, nullptr, k, MROWS, DMODEL, DMODEL, ACT_NONE);
    sgemm_kernel<<<g512, 256>>>(src2, Wv12, bv12, nullptr, v, MROWS, DMODEL, DMODEL, ACT_NONE);
    attn_kernel<<<gAttn, 256, ATTN_SMEM>>>(q, k, v, ctx);
    // x = attn_out + identity (x1)
    sgemm_kernel<<<g512, 256>>>(ctx, Wo, bo, x1, xres, MROWS, DMODEL, DMODEL, ACT_NONE);

    // final LN + MLP; out = x + gelu(h@W1+b1)@W2+b2
    ln_kernel<<<MROWS, 128>>>(xres, lnf_g, lnf_b, x1n);   // reuse x1n
    sgemm_kernel<<<g1024, 256>>>(x1n, W1, b1, nullptr, hbuf, MROWS, DMLP, DMODEL, ACT_GELU);
    sgemm_kernel<<<g512, 256>>>(hbuf, W2, b2, xres, out, MROWS, DMODEL, DMLP, ACT_NONE);
}

// round 2
// speedup vs baseline: 4.6000x; 4.6000x over previous
#include <cuda_runtime.h>
#include <math.h>
#include <stdint.h>

#define BATCH 16
#define SEQ   1024
#define DMODEL 512
#define NHEAD 4
#define HDIM  128
#define MROWS (BATCH * SEQ)   // 16384
#define DMLP  1024

// ---------------- scratch (device globals; no allocation allowed) ----------
__device__ float g_x1n [MROWS * DMODEL];
__device__ float g_x2n [MROWS * DMODEL];
__device__ float g_q   [MROWS * DMODEL];
__device__ float g_k   [MROWS * DMODEL];
__device__ float g_v   [MROWS * DMODEL];
__device__ float g_ctx [MROWS * DMODEL];
__device__ float g_src1[MROWS * DMODEL];
__device__ float g_src2[MROWS * DMODEL];
__device__ float g_xres[MROWS * DMODEL];
__device__ float g_h   [MROWS * DMLP];

// ---------------- tf32 helpers ---------------------------------------------
__device__ __forceinline__ uint32_t f2tf(float f) {
    uint32_t u;
    asm("cvt.rna.tf32.f32 %0, %1;" : "=r"(u) : "f"(f));
    return u;
}

__device__ __forceinline__ void mma_tf32(float* c, const uint32_t* a, const uint32_t* b) {
    asm volatile(
        "mma.sync.aligned.m16n8k8.row.col.f32.tf32.tf32.f32 "
        "{%0,%1,%2,%3}, {%4,%5,%6,%7}, {%8,%9}, {%0,%1,%2,%3};"
        : "+f"(c[0]), "+f"(c[1]), "+f"(c[2]), "+f"(c[3])
        : "r"(a[0]), "r"(a[1]), "r"(a[2]), "r"(a[3]),
          "r"(b[0]), "r"(b[1]));
}

// ---------------- LayerNorm: one block (128 thr) per row of 512 ------------
__global__ void ln_kernel(const float* __restrict__ x,
                          const float* __restrict__ g,
                          const float* __restrict__ b,
                          float* __restrict__ y) {
    int row = blockIdx.x;
    const float* xr = x + (size_t)row * DMODEL;
    float*       yr = y + (size_t)row * DMODEL;
    int t = threadIdx.x;
    float4 v4 = ((const float4*)xr)[t];

    __shared__ float red[4];
    float s = v4.x + v4.y + v4.z + v4.w;
    #pragma unroll
    for (int o = 16; o; o >>= 1) s += __shfl_xor_sync(0xffffffffu, s, o);
    if ((t & 31) == 0) red[t >> 5] = s;
    __syncthreads();
    float mean = (red[0] + red[1] + red[2] + red[3]) * (1.0f / DMODEL);
    __syncthreads();

    float dx = v4.x - mean, dy = v4.y - mean, dz = v4.z - mean, dw = v4.w - mean;
    float vs = dx*dx + dy*dy + dz*dz + dw*dw;
    #pragma unroll
    for (int o = 16; o; o >>= 1) vs += __shfl_xor_sync(0xffffffffu, vs, o);
    if ((t & 31) == 0) red[t >> 5] = vs;
    __syncthreads();
    float var = (red[0] + red[1] + red[2] + red[3]) * (1.0f / DMODEL);
    float inv = rsqrtf(var + 1e-6f);

    float4 g4 = ((const float4*)g)[t];
    float4 b4 = ((const float4*)b)[t];
    float4 o4;
    o4.x = dx * inv * g4.x + b4.x;
    o4.y = dy * inv * g4.y + b4.y;
    o4.z = dz * inv * g4.z + b4.z;
    o4.w = dw * inv * g4.w + b4.w;
    ((float4*)yr)[t] = o4;
}

// ---------------- tf32 tensor-core GEMM ------------------------------------
// C = A[M,K] @ W[K,N] + bias (+resid)(+gelu)
// Block: 256 thr, tile 128(M) x 128(N), K-step 32.
// Warps: 8, grid 2(M) x 4(N); each warp 64x32 via 4x4 m16n8k8 frags.
#define ACT_NONE 0
#define ACT_GELU 1

__global__ __launch_bounds__(256, 2)
void gemm_tc(const float* __restrict__ A, const float* __restrict__ W,
             const float* __restrict__ bias, const float* __restrict__ resid,
             float* __restrict__ C, int M, int N, int K, int act) {
    // A row-major tile: pitch 36 (== 4 mod 32 -> conflict-free a-frags)
    // B row-major tile: pitch 136 (== 8 mod 32 -> conflict-free b-frags)
    __shared__ uint32_t As[128][36];
    __shared__ uint32_t Bs[32][136];

    int tid = threadIdx.x, lane = tid & 31, wid = tid >> 5;
    int m0 = blockIdx.y * 128, n0 = blockIdx.x * 128;
    int wm = (wid & 1) * 64, wn = (wid >> 1) * 32;

    float acc[4][4][4];
    #pragma unroll
    for (int i = 0; i < 4; i++)
        #pragma unroll
        for (int j = 0; j < 4; j++)
            #pragma unroll
            for (int k = 0; k < 4; k++) acc[i][j][k] = 0.f;

    int am = tid >> 3;            // 0..31 (A row within group)
    int ak = (tid & 7) * 4;       // 0..28 (A k-col)
    int bn = (tid & 31) * 4;      // 0..124 (B n-col)
    int bk = tid >> 5;            // 0..7  (B k-row)

    for (int k0 = 0; k0 < K; k0 += 32) {
        #pragma unroll
        for (int i = 0; i < 4; i++) {
            float4 v = *(const float4*)&A[(size_t)(m0 + am + i * 32) * K + k0 + ak];
            uint32_t* d = &As[am + i * 32][ak];
            d[0] = f2tf(v.x); d[1] = f2tf(v.y); d[2] = f2tf(v.z); d[3] = f2tf(v.w);
        }
        #pragma unroll
        for (int i = 0; i < 4; i++) {
            float4 v = *(const float4*)&W[(size_t)(k0 + bk + i * 8) * N + n0 + bn];
            uint32_t* d = &Bs[bk + i * 8][bn];
            d[0] = f2tf(v.x); d[1] = f2tf(v.y); d[2] = f2tf(v.z); d[3] = f2tf(v.w);
        }
        __syncthreads();

        int r4 = lane >> 2, c4 = lane & 3;
        #pragma unroll
        for (int ks = 0; ks < 4; ks++) {
            int kk = ks * 8 + c4;
            uint32_t a[4][4], b[4][2];
            #pragma unroll
            for (int mf = 0; mf < 4; mf++) {
                int m = wm + mf * 16 + r4;
                a[mf][0] = As[m][kk];
                a[mf][1] = As[m + 8][kk];
                a[mf][2] = As[m][kk + 4];
                a[mf][3] = As[m + 8][kk + 4];
            }
            #pragma unroll
            for (int nf = 0; nf < 4; nf++) {
                int n = wn + nf * 8 + r4;
                b[nf][0] = Bs[kk][n];
                b[nf][1] = Bs[kk + 4][n];
            }
            #pragma unroll
            for (int mf = 0; mf < 4; mf++)
                #pragma unroll
                for (int nf = 0; nf < 4; nf++)
                    mma_tf32(acc[mf][nf], a[mf], b[nf]);
        }
        __syncthreads();
    }

    // epilogue
    int r4 = lane >> 2, c2 = (lane & 3) * 2;
    #pragma unroll
    for (int mf = 0; mf < 4; mf++) {
        #pragma unroll
        for (int nf = 0; nf < 4; nf++) {
            int row = m0 + wm + mf * 16 + r4;
            int col = n0 + wn + nf * 8 + c2;
            float2 bi = *(const float2*)&bias[col];
            #pragma unroll
            for (int hh = 0; hh < 2; hh++) {
                int r = row + hh * 8;
                float v0 = acc[mf][nf][hh * 2 + 0] + bi.x;
                float v1 = acc[mf][nf][hh * 2 + 1] + bi.y;
                if (resid) {
                    float2 rr = *(const float2*)&resid[(size_t)r * N + col];
                    v0 += rr.x; v1 += rr.y;
                }
                if (act == ACT_GELU) {
                    v0 = 0.5f * v0 * (1.0f + erff(v0 * 0.70710678118654752f));
                    v1 = 0.5f * v1 * (1.0f + erff(v1 * 0.70710678118654752f));
                }
                float2 o2 = make_float2(v0, v1);
                *(float2*)&C[(size_t)r * N + col] = o2;
            }
        }
    }
}

// ---------------- tf32 tensor-core flash attention -------------------------
// grid (SEQ/128, NHEAD, BATCH), 256 thr (8 warps). Each warp owns 16 q rows.
// K chunks of 64. Q,K,V,P all row-major SMEM, pitches chosen conflict-free.
#define ATT_QW (128 * 132)
#define ATT_KW (64 * 132)
#define ATT_VW (64 * 136)
#define ATT_PW (128 * 68)
#define ATT_SMEM_BYTES ((ATT_QW + ATT_KW + ATT_VW + ATT_PW) * 4)

__global__ __launch_bounds__(256, 1)
void attn_tc(const float* __restrict__ Q, const float* __restrict__ K,
             const float* __restrict__ V, float* __restrict__ O) {
    extern __shared__ uint32_t sm[];
    uint32_t* Qs = sm;                  // [128][132]  q-rows x hd
    uint32_t* Ks = Qs + ATT_QW;         // [64][132]   keys  x hd
    uint32_t* Vs = Ks + ATT_KW;         // [64][136]   keys  x hd
    uint32_t* Ps = Vs + ATT_VW;         // [128][68]   q-rows x keys

    int tid = threadIdx.x, lane = tid & 31, wid = tid >> 5;
    int q0 = blockIdx.x * 128, h = blockIdx.y, b = blockIdx.z;
    size_t gq = ((size_t)b * SEQ + q0) * DMODEL + (size_t)h * HDIM;
    const float scale = 0.08838834764831845f;  // 1/sqrt(128)

    int d4 = lane * 4;        // 0..124
    int rr = tid >> 5;        // warp id = row group

    // stage Q (scaled) once
    #pragma unroll
    for (int i = 0; i < 16; i++) {
        int qq = rr + i * 8;
        float4 v = *(const float4*)&Q[gq + (size_t)qq * DMODEL + d4];
        uint32_t* d = &Qs[qq * 132 + d4];
        d[0] = f2tf(v.x * scale); d[1] = f2tf(v.y * scale);
        d[2] = f2tf(v.z * scale); d[3] = f2tf(v.w * scale);
    }

    float mrow[2] = {-1e30f, -1e30f}, lrow[2] = {0.f, 0.f};
    float o[16][4];
    #pragma unroll
    for (int i = 0; i < 16; i++)
        #pragma unroll
        for (int j = 0; j < 4; j++) o[i][j] = 0.f;

    int r4 = lane >> 2, c4 = lane & 3;
    int mq = wid * 16 + r4;

    for (int kc = 0; kc < SEQ; kc += 64) {
        __syncthreads();
        size_t gk = ((size_t)b * SEQ + kc) * DMODEL + (size_t)h * HDIM;
        #pragma unroll
        for (int i = 0; i < 8; i++) {
            int kr = rr + i * 8;
            float4 kv = *(const float4*)&K[gk + (size_t)kr * DMODEL + d4];
            float4 vv = *(const float4*)&V[gk + (size_t)kr * DMODEL + d4];
            uint32_t* dk = &Ks[kr * 132 + d4];
            dk[0] = f2tf(kv.x); dk[1] = f2tf(kv.y); dk[2] = f2tf(kv.z); dk[3] = f2tf(kv.w);
            uint32_t* dv = &Vs[kr * 136 + d4];
            dv[0] = f2tf(vv.x); dv[1] = f2tf(vv.y); dv[2] = f2tf(vv.z); dv[3] = f2tf(vv.w);
        }
        __syncthreads();

        // S = Q @ K^T : warp computes 16 x 64
        float s[8][4];
        #pragma unroll
        for (int nf = 0; nf < 8; nf++)
            #pragma unroll
            for (int j = 0; j < 4; j++) s[nf][j] = 0.f;

        #pragma unroll
        for (int ks = 0; ks < 16; ks++) {
            int kk = ks * 8 + c4;
            uint32_t a[4];
            a[0] = Qs[mq * 132 + kk];
            a[1] = Qs[(mq + 8) * 132 + kk];
            a[2] = Qs[mq * 132 + kk + 4];
            a[3] = Qs[(mq + 8) * 132 + kk + 4];
            #pragma unroll
            for (int nf = 0; nf < 8; nf++) {
                int n = nf * 8 + r4;
                uint32_t bb[2];
                bb[0] = Ks[n * 132 + kk];       // B[k][n] = K[key=n][d=k]
                bb[1] = Ks[n * 132 + kk + 4];
                mma_tf32(s[nf], a, bb);
            }
        }

        // online softmax per row-half
        #pragma unroll
        for (int h2 = 0; h2 < 2; h2++) {
            int base = h2 * 2;
            float mx = -1e30f;
            #pragma unroll
            for (int nf = 0; nf < 8; nf++)
                mx = fmaxf(mx, fmaxf(s[nf][base], s[nf][base + 1]));
            mx = fmaxf(mx, __shfl_xor_sync(0xffffffffu, mx, 1));
            mx = fmaxf(mx, __shfl_xor_sync(0xffffffffu, mx, 2));
            float mnew = fmaxf(mrow[h2], mx);
            float corr = __expf(mrow[h2] - mnew);
            mrow[h2] = mnew;

            int qrow = mq + 8 * h2;
            float ps = 0.f;
            #pragma unroll
            for (int nf = 0; nf < 8; nf++) {
                float p0 = __expf(s[nf][base]     - mnew);
                float p1 = __expf(s[nf][base + 1] - mnew);
                ps += p0 + p1;
                int key = nf * 8 + 2 * c4;
                Ps[qrow * 68 + key]     = f2tf(p0);
                Ps[qrow * 68 + key + 1] = f2tf(p1);
            }
            ps += __shfl_xor_sync(0xffffffffu, ps, 1);
            ps += __shfl_xor_sync(0xffffffffu, ps, 2);
            lrow[h2] = lrow[h2] * corr + ps;
            #pragma unroll
            for (int nf = 0; nf < 16; nf++) {
                o[nf][base]     *= corr;
                o[nf][base + 1] *= corr;
            }
        }
        __syncwarp();

        // O += P @ V : warp 16 x 128, K = 64 keys
        #pragma unroll
        for (int ks = 0; ks < 8; ks++) {
            int kk = ks * 8 + c4;
            uint32_t a[4];
            a[0] = Ps[mq * 68 + kk];
            a[1] = Ps[(mq + 8) * 68 + kk];
            a[2] = Ps[mq * 68 + kk + 4];
            a[3] = Ps[(mq + 8) * 68 + kk + 4];
            #pragma unroll
            for (int nf = 0; nf < 16; nf++) {
                int n = nf * 8 + r4;
                uint32_t bb[2];
                bb[0] = Vs[kk * 136 + n];
                bb[1] = Vs[(kk + 4) * 136 + n];
                mma_tf32(o[nf], a, bb);
            }
        }
    }

    float inv0 = 1.0f / lrow[0], inv1 = 1.0f / lrow[1];
    #pragma unroll
    for (int nf = 0; nf < 16; nf++) {
        int col = nf * 8 + 2 * c4;
        size_t base0 = gq + (size_t)mq * DMODEL + col;
        float2 o0 = make_float2(o[nf][0] * inv0, o[nf][1] * inv0);
        float2 o1 = make_float2(o[nf][2] * inv1, o[nf][3] * inv1);
        *(float2*)&O[base0]                 = o0;
        *(float2*)&O[base0 + 8 * DMODEL]    = o1;
    }
}

// ---------------- driver ----------------------------------------------------
extern "C" void kernel_launch(void* const* d_in, const int* in_sizes, int n_in,
                              void* d_out, int out_size) {
    const float* x1    = (const float*)d_in[0];
    const float* x2    = (const float*)d_in[1];
    const float* ln1_g = (const float*)d_in[2];
    const float* ln1_b = (const float*)d_in[3];
    const float* ln2_g = (const float*)d_in[4];
    const float* ln2_b = (const float*)d_in[5];
    const float* lnf_g = (const float*)d_in[6];
    const float* lnf_b = (const float*)d_in[7];
    const float* Wq1  = (const float*)d_in[8];   const float* bq1  = (const float*)d_in[9];
    const float* Wk1  = (const float*)d_in[10];  const float* bk1  = (const float*)d_in[11];
    const float* Wv1  = (const float*)d_in[12];  const float* bv1  = (const float*)d_in[13];
    const float* Wq2  = (const float*)d_in[14];  const float* bq2  = (const float*)d_in[15];
    const float* Wk2  = (const float*)d_in[16];  const float* bk2  = (const float*)d_in[17];
    const float* Wv2  = (const float*)d_in[18];  const float* bv2  = (const float*)d_in[19];
    const float* Wq12 = (const float*)d_in[20];  const float* bq12 = (const float*)d_in[21];
    const float* Wk12 = (const float*)d_in[22];  const float* bk12 = (const float*)d_in[23];
    const float* Wv12 = (const float*)d_in[24];  const float* bv12 = (const float*)d_in[25];
    const float* Wo   = (const float*)d_in[26];  const float* bo   = (const float*)d_in[27];
    const float* W1   = (const float*)d_in[28];  const float* b1   = (const float*)d_in[29];
    const float* W2   = (const float*)d_in[30];  const float* b2   = (const float*)d_in[31];
    float* out = (float*)d_out;

    float *x1n, *x2n, *q, *k, *v, *ctx, *src1, *src2, *xres, *hbuf;
    cudaGetSymbolAddress((void**)&x1n,  g_x1n);
    cudaGetSymbolAddress((void**)&x2n,  g_x2n);
    cudaGetSymbolAddress((void**)&q,    g_q);
    cudaGetSymbolAddress((void**)&k,    g_k);
    cudaGetSymbolAddress((void**)&v,    g_v);
    cudaGetSymbolAddress((void**)&ctx,  g_ctx);
    cudaGetSymbolAddress((void**)&src1, g_src1);
    cudaGetSymbolAddress((void**)&src2, g_src2);
    cudaGetSymbolAddress((void**)&xres, g_xres);
    cudaGetSymbolAddress((void**)&hbuf, g_h);

    cudaFuncSetAttribute(attn_tc, cudaFuncAttributeMaxDynamicSharedMemorySize,
                         ATT_SMEM_BYTES);

    dim3 gAttn(SEQ / 128, NHEAD, BATCH);
    dim3 g512 (DMODEL / 128, MROWS / 128);   // (4, 128)
    dim3 g1024(DMLP   / 128, MROWS / 128);   // (8, 128)

    // normalize both streams
    ln_kernel<<<MROWS, 128>>>(x1, ln1_g, ln1_b, x1n);
    ln_kernel<<<MROWS, 128>>>(x2, ln2_g, ln2_b, x2n);

    // stream-1 self-attention
    gemm_tc<<<g512, 256>>>(x1n, Wq1, bq1, nullptr, q, MROWS, DMODEL, DMODEL, ACT_NONE);
    gemm_tc<<<g512, 256>>>(x1n, Wk1, bk1, nullptr, k, MROWS, DMODEL, DMODEL, ACT_NONE);
    gemm_tc<<<g512, 256>>>(x1n, Wv1, bv1, nullptr, v, MROWS, DMODEL, DMODEL, ACT_NONE);
    attn_tc<<<gAttn, 256, ATT_SMEM_BYTES>>>(q, k, v, ctx);
    gemm_tc<<<g512, 256>>>(ctx, Wo, bo, x1n, src1, MROWS, DMODEL, DMODEL, ACT_NONE);

    // stream-2 self-attention
    gemm_tc<<<g512, 256>>>(x2n, Wq2, bq2, nullptr, q, MROWS, DMODEL, DMODEL, ACT_NONE);
    gemm_tc<<<g512, 256>>>(x2n, Wk2, bk2, nullptr, k, MROWS, DMODEL, DMODEL, ACT_NONE);
    gemm_tc<<<g512, 256>>>(x2n, Wv2, bv2, nullptr, v, MROWS, DMODEL, DMODEL, ACT_NONE);
    attn_tc<<<gAttn, 256, ATT_SMEM_BYTES>>>(q, k, v, ctx);
    gemm_tc<<<g512, 256>>>(ctx, Wo, bo, x2n, src2, MROWS, DMODEL, DMODEL, ACT_NONE);

    // cross attention: Q from src1, K/V from src2
    gemm_tc<<<g512, 256>>>(src1, Wq12, bq12, nullptr, q, MROWS, DMODEL, DMODEL, ACT_NONE);
    gemm_tc<<<g512, 256>>>(src2, Wk12, bk12, nullptr, k, MROWS, DMODEL, DMODEL, ACT_NONE);
    gemm_tc<<<g512, 256>>>(src2, Wv12, bv12, nullptr, v, MROWS, DMODEL, DMODEL, ACT_NONE);
    attn_tc<<<gAttn, 256, ATT_SMEM_BYTES>>>(q, k, v, ctx);
    gemm_tc<<<g512, 256>>>(ctx, Wo, bo, x1, xres, MROWS, DMODEL, DMODEL, ACT_NONE);

    // final LN + MLP; out = x + gelu(h@W1+b1)@W2+b2
    ln_kernel<<<MROWS, 128>>>(xres, lnf_g, lnf_b, x1n);
    gemm_tc<<<g1024, 256>>>(x1n, W1, b1, nullptr, hbuf, MROWS, DMLP, DMODEL, ACT_GELU);
    gemm_tc<<<g512, 256>>>(hbuf, W2, b2, xres, out, MROWS, DMODEL, DMLP, ACT_NONE);
}